// round 15
// baseline (speedup 1.0000x reference)
#include <cuda_runtime.h>
#include <cuda_fp16.h>

#define NN 100000
#define NE 3200000
#define H  64
#define SCAN_B 1024
#define NB 98                      // ceil(NN / SCAN_B)
#define PAD 68                     // 64 + 4: 16B-aligned, conflict-free LDS.128

// -------- device scratch (no allocations allowed) --------
__device__ int     g_cnt[NN];
__device__ int     g_row[NN + 1];
__device__ int     g_pos[NN];
__device__ float   g_dis[NN];
__device__ unsigned long long g_look[NB];   // lookback: status(2b)<<62 | value
__device__ int2    g_e[NE];          // CSR slot: (src, bitcast weight)
__device__ __half2 g_h1h[NN * 32];   // h1 fp16 pairs (cols 2l, 2l+1)
__device__ __half  g_Ph[NN * H];     // fp16: h2 @ Wm1[0:64] + bm1
__device__ __half  g_Qh[NN * H];     // fp16: h2 @ Wm1[64:128]

// -------- 1: histogram of in-degrees --------
__global__ void k_hist(const int* __restrict__ dst) {
    int e = blockIdx.x * blockDim.x + threadIdx.x;
    if (e < NE) atomicAdd(&g_cnt[dst[e]], 1);
}

// -------- 2: single-kernel exclusive scan (decoupled lookback) --------
__global__ void k_scan() {
    __shared__ int ss[SCAN_B];
    __shared__ int s_base;
    int tid = threadIdx.x, bid = blockIdx.x;
    int i = bid * SCAN_B + tid;
    int v = (i < NN) ? g_cnt[i] : 0;
    ss[tid] = v;
    __syncthreads();
#pragma unroll
    for (int off = 1; off < SCAN_B; off <<= 1) {
        int t = (tid >= off) ? ss[tid - off] : 0;
        __syncthreads();
        ss[tid] += t;
        __syncthreads();
    }
    int incl  = ss[tid];
    int total = ss[SCAN_B - 1];
    if (tid == 0) {
        unsigned long long pub = (bid == 0)
            ? ((2ULL << 62) | (unsigned long long)(unsigned)total)
            : ((1ULL << 62) | (unsigned long long)(unsigned)total);
        atomicExch(&g_look[bid], pub);
        int base = 0;
        if (bid > 0) {
            int j = bid - 1;
            while (true) {
                unsigned long long v2;
                do { v2 = atomicOr(&g_look[j], 0ULL); } while ((v2 >> 62) == 0ULL);
                base += (int)(v2 & 0xFFFFFFFFULL);
                if ((v2 >> 62) == 2ULL) break;
                j--;
            }
            atomicExch(&g_look[bid],
                       (2ULL << 62) | (unsigned long long)(unsigned)(base + total));
        }
        s_base = base;
    }
    __syncthreads();
    int base = s_base;
    if (i < NN) {
        int r = incl - v + base;
        g_row[i] = r;
        g_pos[i] = r;
        g_dis[i] = rsqrtf((float)(g_cnt[i] + 1));   // +1 self-loop
    }
    if (i == 0) g_row[NN] = NE;
}

// -------- 3: CSR placement --------
__global__ void k_place(const int* __restrict__ src, const int* __restrict__ dst) {
    int e = blockIdx.x * blockDim.x + threadIdx.x;
    if (e >= NE) return;
    int s = src[e], d = dst[e];
    int idx = atomicAdd(&g_pos[d], 1);
    int2 ev; ev.x = s; ev.y = __float_as_int(g_dis[s] * g_dis[d]);
    g_e[idx] = ev;
}

// -------- 4: fused layer 1: warp per node; h1 out in fp16 pairs --------
__global__ void k_aggx_h1(const float* __restrict__ x,
                          const float* __restrict__ W1, const float* __restrict__ b1) {
    int w = (blockIdx.x * blockDim.x + threadIdx.x) >> 5;
    if (w >= NN) return;
    int lane = threadIdx.x & 31;
    int r0 = g_row[w], r1 = g_row[w + 1];
    float ax = 0.f, ay = 0.f, az = 0.f, aw = 0.f;
#pragma unroll 4
    for (int r = r0 + lane; r < r1; r += 32) {
        int2 ev = g_e[r];
        float ww = __int_as_float(ev.y);
        float4 xv = *reinterpret_cast<const float4*>(x + (size_t)ev.x * 4);
        ax += xv.x * ww; ay += xv.y * ww; az += xv.z * ww; aw += xv.w * ww;
    }
    if (lane == 0) {                     // self-loop
        float dd = g_dis[w]; dd *= dd;
        float4 xv = *reinterpret_cast<const float4*>(x + (size_t)w * 4);
        ax += dd * xv.x; ay += dd * xv.y; az += dd * xv.z; aw += dd * xv.w;
    }
#pragma unroll
    for (int off = 16; off >= 1; off >>= 1) {
        ax += __shfl_xor_sync(0xffffffffu, ax, off);
        ay += __shfl_xor_sync(0xffffffffu, ay, off);
        az += __shfl_xor_sync(0xffffffffu, az, off);
        aw += __shfl_xor_sync(0xffffffffu, aw, off);
    }
    int c0 = 2 * lane, c1 = c0 + 1;
    float s0 = ax * __ldg(W1 + c0) + ay * __ldg(W1 + 64 + c0)
             + az * __ldg(W1 + 128 + c0) + aw * __ldg(W1 + 192 + c0) + __ldg(b1 + c0);
    float s1 = ax * __ldg(W1 + c1) + ay * __ldg(W1 + 64 + c1)
             + az * __ldg(W1 + 128 + c1) + aw * __ldg(W1 + 192 + c1) + __ldg(b1 + c1);
    g_h1h[(size_t)w * 32 + lane] = __floats2half2_rn(fmaxf(s0, 0.f), fmaxf(s1, 0.f));
}

// -------- 5: fused layer-2 agg (edge-balanced) + tiled dense + P,Q --------
// Block: 512 thr = 16 warps, 16 nodes. Warps split the block's whole edge
// range evenly; per-node partials flushed to smem atomically at boundaries.
__global__ void k_agg_dense2(const float* __restrict__ W2, const float* __restrict__ b2,
                             const float* __restrict__ Wm1, const float* __restrict__ bm1) {
    __shared__ float sWa[64 * PAD];
    __shared__ float sWb[64 * PAD];
    __shared__ float sIn[16 * PAD];
    __shared__ int   sRow[17];
    int tid  = threadIdx.x;
    int nb   = blockIdx.x * 16;
    int wid  = tid >> 5, lane = tid & 31;

    if (tid < 17) sRow[tid] = g_row[nb + tid];
    for (int i = tid; i < 16 * PAD; i += 512) sIn[i] = 0.f;
    __syncthreads();

    // ---- stage A: balanced edge aggregation ----
    {
        int R0 = sRow[0], R1 = sRow[16];
        int total = R1 - R0;
        int chunk = (total + 15) >> 4;
        int s = R0 + wid * chunk;
        int epos = s + chunk; if (epos > R1) epos = R1;
        if (s < epos) {
            int lo = 0, hi = 16;
            while (lo < hi) {
                int mid = (lo + hi + 1) >> 1;
                if (sRow[mid] <= s) lo = mid; else hi = mid - 1;
            }
            int cur = lo;
            int r = s;
            while (r < epos) {
                while (r >= sRow[cur + 1]) cur++;
                int seg = sRow[cur + 1]; if (seg > epos) seg = epos;
                float a0 = 0.f, a1 = 0.f;
                for (; r + 3 < seg; r += 4) {
                    int2 ev[4];
#pragma unroll
                    for (int u = 0; u < 4; u++) ev[u] = g_e[r + u];
                    __half2 hv[4];
#pragma unroll
                    for (int u = 0; u < 4; u++) hv[u] = g_h1h[(size_t)ev[u].x * 32 + lane];
#pragma unroll
                    for (int u = 0; u < 4; u++) {
                        float2 v = __half22float2(hv[u]);
                        float we = __int_as_float(ev[u].y);
                        a0 += v.x * we;
                        a1 += v.y * we;
                    }
                }
                for (; r < seg; r++) {
                    int2 ev = g_e[r];
                    float2 v = __half22float2(g_h1h[(size_t)ev.x * 32 + lane]);
                    float we = __int_as_float(ev.y);
                    a0 += v.x * we;
                    a1 += v.y * we;
                }
                atomicAdd(&sIn[cur * PAD + 2 * lane],     a0);
                atomicAdd(&sIn[cur * PAD + 2 * lane + 1], a1);
            }
        }
        int node = nb + wid;                 // self-loop term
        float dd = g_dis[node]; dd *= dd;
        float2 v = __half22float2(g_h1h[(size_t)node * 32 + lane]);
        atomicAdd(&sIn[wid * PAD + 2 * lane],     v.x * dd);
        atomicAdd(&sIn[wid * PAD + 2 * lane + 1], v.y * dd);
    }
    for (int i = tid; i < 4096; i += 512)
        sWa[(i & 63) * PAD + (i >> 6)] = W2[i];
    __syncthreads();

    // ---- stage B: h2 = relu(tmp @ W2 + b2), register-tiled ----
    int col = tid & 63, ng = tid >> 6;
    float hreg[2];
    {
        const float4* wp = reinterpret_cast<const float4*>(sWa + col * PAD);
        const float4* i0 = reinterpret_cast<const float4*>(sIn + ng * PAD);
        const float4* i1 = reinterpret_cast<const float4*>(sIn + (ng + 8) * PAD);
        float a0 = 0.f, a1 = 0.f;
#pragma unroll
        for (int k4 = 0; k4 < 16; k4++) {
            float4 w = wp[k4];
            float4 v0 = i0[k4];
            float4 v1 = i1[k4];
            a0 += v0.x * w.x + v0.y * w.y + v0.z * w.z + v0.w * w.w;
            a1 += v1.x * w.x + v1.y * w.y + v1.z * w.z + v1.w * w.w;
        }
        float bb = __ldg(b2 + col);
        hreg[0] = fmaxf(a0 + bb, 0.f);
        hreg[1] = fmaxf(a1 + bb, 0.f);
    }
    __syncthreads();

    // ---- stage C: P,Q = h2 @ Wm1 halves, register-tiled ----
    sIn[ng * PAD + col]       = hreg[0];
    sIn[(ng + 8) * PAD + col] = hreg[1];
    for (int i = tid; i < 4096; i += 512) {
        int k = i >> 6, c = i & 63;
        sWa[c * PAD + k] = Wm1[i];
        sWb[c * PAD + k] = Wm1[4096 + i];
    }
    __syncthreads();
    {
        const float4* wa = reinterpret_cast<const float4*>(sWa + col * PAD);
        const float4* wb = reinterpret_cast<const float4*>(sWb + col * PAD);
        const float4* i0 = reinterpret_cast<const float4*>(sIn + ng * PAD);
        const float4* i1 = reinterpret_cast<const float4*>(sIn + (ng + 8) * PAD);
        float p0 = 0.f, p1 = 0.f, q0 = 0.f, q1 = 0.f;
#pragma unroll
        for (int k4 = 0; k4 < 16; k4++) {
            float4 a = wa[k4];
            float4 b = wb[k4];
            float4 v0 = i0[k4];
            float4 v1 = i1[k4];
            p0 += v0.x * a.x + v0.y * a.y + v0.z * a.z + v0.w * a.w;
            q0 += v0.x * b.x + v0.y * b.y + v0.z * b.z + v0.w * b.w;
            p1 += v1.x * a.x + v1.y * a.y + v1.z * a.z + v1.w * a.w;
            q1 += v1.x * b.x + v1.y * b.y + v1.z * b.z + v1.w * b.w;
        }
        float bmv = __ldg(bm1 + col);
        size_t o0 = (size_t)(nb + ng) * 64 + col;
        size_t o1 = (size_t)(nb + ng + 8) * 64 + col;
        g_Ph[o0] = __float2half(p0 + bmv);
        g_Qh[o0] = __float2half(q0);
        g_Ph[o1] = __float2half(p1 + bmv);
        g_Qh[o1] = __float2half(q1);
    }
}

// -------- 6: edge epilogue, 8 lanes/edge, uint4 fp16 loads, fp32 math -------
// out[e] = relu(P[s]+Q[d]+ea@Wea) @ Wm2 + bm2
__global__ void k_edge(const int* __restrict__ src, const int* __restrict__ dst,
                       const float* __restrict__ ea,
                       const float* __restrict__ Wm1,
                       const float* __restrict__ Wm2, const float* __restrict__ bm2,
                       float* __restrict__ out) {
    int l  = threadIdx.x & 7;
    int c0 = l * 8;                       // 8 columns per lane
    float w0[8], w1[8], w2[8], w3[8], wo[8];
#pragma unroll
    for (int j = 0; j < 8; j++) {
        w0[j] = __ldg(Wm1 + 128 * 64 + c0 + j);
        w1[j] = __ldg(Wm1 + 129 * 64 + c0 + j);
        w2[j] = __ldg(Wm1 + 130 * 64 + c0 + j);
        w3[j] = __ldg(Wm1 + 131 * 64 + c0 + j);
        wo[j] = __ldg(Wm2 + c0 + j);
    }
    float ob = bm2[0];

    int grp  = (blockIdx.x * blockDim.x + threadIdx.x) >> 3;
    int ngrp = (gridDim.x * blockDim.x) >> 3;
    for (int e0 = grp; e0 < NE; e0 += 4 * ngrp) {
        float part[4];
        int   ee[4];
        bool  ok[4];
#pragma unroll
        for (int u = 0; u < 4; u++) {
            int e = e0 + u * ngrp;
            ok[u] = (e < NE);
            ee[u] = ok[u] ? e : e0;
            int s = src[ee[u]], d = dst[ee[u]];
            uint4 pv = *reinterpret_cast<const uint4*>(g_Ph + (size_t)s * 64 + c0);
            uint4 qv = *reinterpret_cast<const uint4*>(g_Qh + (size_t)d * 64 + c0);
            float4 a = *reinterpret_cast<const float4*>(ea + (size_t)ee[u] * 4);
            const __half2* ph = reinterpret_cast<const __half2*>(&pv);
            const __half2* qh = reinterpret_cast<const __half2*>(&qv);
            float acc = 0.f;
#pragma unroll
            for (int j = 0; j < 4; j++) {
                float2 p = __half22float2(ph[j]);
                float2 q = __half22float2(qh[j]);
                float za = p.x + q.x + a.x * w0[2*j]   + a.y * w1[2*j]   + a.z * w2[2*j]   + a.w * w3[2*j];
                float zb = p.y + q.y + a.x * w0[2*j+1] + a.y * w1[2*j+1] + a.z * w2[2*j+1] + a.w * w3[2*j+1];
                za = fmaxf(za, 0.f);
                zb = fmaxf(zb, 0.f);
                acc += za * wo[2*j] + zb * wo[2*j+1];
            }
            part[u] = acc;
        }
#pragma unroll
        for (int off = 4; off >= 1; off >>= 1) {
#pragma unroll
            for (int u = 0; u < 4; u++)
                part[u] += __shfl_down_sync(0xffffffffu, part[u], off, 8);
        }
        if (l == 0) {
#pragma unroll
            for (int u = 0; u < 4; u++)
                if (ok[u]) out[ee[u]] = part[u] + ob;
        }
    }
}

extern "C" void kernel_launch(void* const* d_in, const int* in_sizes, int n_in,
                              void* d_out, int out_size) {
    const float* x   = (const float*)d_in[0];
    const int*   ei  = (const int*)  d_in[1];   // [2, NE] int32
    const float* ea  = (const float*)d_in[2];
    const float* W1  = (const float*)d_in[3];
    const float* b1  = (const float*)d_in[4];
    const float* W2  = (const float*)d_in[5];
    const float* b2  = (const float*)d_in[6];
    const float* Wm1 = (const float*)d_in[7];
    const float* bm1 = (const float*)d_in[8];
    const float* Wm2 = (const float*)d_in[9];
    const float* bm2 = (const float*)d_in[10];
    float* out = (float*)d_out;

    const int* src = ei;
    const int* dst = ei + NE;

    void* p_cnt  = nullptr;
    void* p_look = nullptr;
    cudaGetSymbolAddress(&p_cnt,  g_cnt);
    cudaGetSymbolAddress(&p_look, g_look);
    cudaMemsetAsync(p_cnt,  0, NN * sizeof(int), 0);
    cudaMemsetAsync(p_look, 0, NB * sizeof(unsigned long long), 0);

    const int TB = 256;
    int ne_blk  = (NE + TB - 1) / TB;
    int agg_blk = (NN + 7) / 8;

    k_hist <<<ne_blk, TB>>>(dst);                        // kernel 1
    k_scan <<<NB, SCAN_B>>>();                           // kernel 2
    k_place<<<ne_blk, TB>>>(src, dst);                   // kernel 3
    k_aggx_h1<<<agg_blk, TB>>>(x, W1, b1);               // kernel 4 (capture slot)
    k_agg_dense2<<<NN / 16, 512>>>(W2, b2, Wm1, bm1);    // kernel 5
    k_edge <<<1184, TB>>>(src, dst, ea, Wm1, Wm2, bm2, out);  // kernel 6
}

// round 16
// speedup vs baseline: 1.0031x; 1.0031x over previous
#include <cuda_runtime.h>
#include <cuda_fp16.h>

#define NN 100000
#define NE 3200000
#define H  64
#define SCAN_B 1024
#define NB 98                      // ceil(NN / SCAN_B)
#define PAD 68                     // 64 + 4: 16B-aligned, conflict-free LDS.128

// -------- device scratch (no allocations allowed; zero-initialized at load) --------
__device__ int      g_cnt[NN];       // self-cleaning: k_scan zeroes after reading
__device__ int      g_row[NN + 1];
__device__ int      g_pos[NN];
__device__ float    g_dis[NN];
__device__ unsigned g_epoch;         // bumped once per launch by k_hist
__device__ unsigned long long g_look[NB];   // epoch<<48 | status<<46 | value
__device__ int2     g_e[NE];         // CSR slot: (src, bitcast weight)
__device__ __half2  g_h1h[NN * 32];  // h1 fp16 pairs (cols 2l, 2l+1)
__device__ __half   g_Ph[NN * H];    // fp16: h2 @ Wm1[0:64] + bm1
__device__ __half   g_Qh[NN * H];    // fp16: h2 @ Wm1[64:128]

// -------- 1: histogram of in-degrees (+ epoch bump) --------
__global__ void k_hist(const int* __restrict__ dst) {
    if (blockIdx.x == 0 && threadIdx.x == 0) g_epoch = g_epoch + 1;
    int e = blockIdx.x * blockDim.x + threadIdx.x;
    if (e < NE) atomicAdd(&g_cnt[dst[e]], 1);
}

// -------- 2: single-kernel exclusive scan (epoch-tagged decoupled lookback) --------
// Fuses: dis = rsqrt(deg+1), pos init, row[NN], g_cnt self-clean.
__global__ void k_scan() {
    __shared__ int ss[SCAN_B];
    __shared__ int s_base;
    int tid = threadIdx.x, bid = blockIdx.x;
    int i = bid * SCAN_B + tid;
    int v = 0;
    if (i < NN) {
        v = g_cnt[i];
        g_cnt[i] = 0;                 // self-clean for next graph replay
    }
    ss[tid] = v;
    __syncthreads();
#pragma unroll
    for (int off = 1; off < SCAN_B; off <<= 1) {
        int t = (tid >= off) ? ss[tid - off] : 0;
        __syncthreads();
        ss[tid] += t;
        __syncthreads();
    }
    int incl  = ss[tid];
    int total = ss[SCAN_B - 1];
    if (tid == 0) {
        unsigned long long ep = (unsigned long long)(g_epoch & 0xFFFFu) << 48;
        unsigned long long st = (bid == 0) ? (2ULL << 46) : (1ULL << 46);
        atomicExch(&g_look[bid], ep | st | (unsigned long long)(unsigned)total);
        int base = 0;
        if (bid > 0) {
            int j = bid - 1;
            while (true) {
                unsigned long long v2;
                do {
                    v2 = atomicOr(&g_look[j], 0ULL);
                } while ((v2 >> 48) != (ep >> 48) || ((v2 >> 46) & 3ULL) == 0ULL);
                base += (int)(v2 & 0xFFFFFFFFULL);
                if (((v2 >> 46) & 3ULL) == 2ULL) break;
                j--;
            }
            atomicExch(&g_look[bid],
                       ep | (2ULL << 46) | (unsigned long long)(unsigned)(base + total));
        }
        s_base = base;
    }
    __syncthreads();
    int base = s_base;
    if (i < NN) {
        int r = incl - v + base;
        g_row[i] = r;
        g_pos[i] = r;
        g_dis[i] = rsqrtf((float)(v + 1));   // +1 self-loop
    }
    if (i == 0) g_row[NN] = NE;
}

// -------- 3: CSR placement --------
__global__ void k_place(const int* __restrict__ src, const int* __restrict__ dst) {
    int e = blockIdx.x * blockDim.x + threadIdx.x;
    if (e >= NE) return;
    int s = src[e], d = dst[e];
    int idx = atomicAdd(&g_pos[d], 1);
    int2 ev; ev.x = s; ev.y = __float_as_int(g_dis[s] * g_dis[d]);
    g_e[idx] = ev;
}

// -------- 4: fused layer 1: warp per node; h1 out in fp16 pairs --------
__global__ void k_aggx_h1(const float* __restrict__ x,
                          const float* __restrict__ W1, const float* __restrict__ b1) {
    int w = (blockIdx.x * blockDim.x + threadIdx.x) >> 5;
    if (w >= NN) return;
    int lane = threadIdx.x & 31;
    int r0 = g_row[w], r1 = g_row[w + 1];
    float ax = 0.f, ay = 0.f, az = 0.f, aw = 0.f;
#pragma unroll 4
    for (int r = r0 + lane; r < r1; r += 32) {
        int2 ev = g_e[r];
        float ww = __int_as_float(ev.y);
        float4 xv = *reinterpret_cast<const float4*>(x + (size_t)ev.x * 4);
        ax += xv.x * ww; ay += xv.y * ww; az += xv.z * ww; aw += xv.w * ww;
    }
    if (lane == 0) {                     // self-loop
        float dd = g_dis[w]; dd *= dd;
        float4 xv = *reinterpret_cast<const float4*>(x + (size_t)w * 4);
        ax += dd * xv.x; ay += dd * xv.y; az += dd * xv.z; aw += dd * xv.w;
    }
#pragma unroll
    for (int off = 16; off >= 1; off >>= 1) {
        ax += __shfl_xor_sync(0xffffffffu, ax, off);
        ay += __shfl_xor_sync(0xffffffffu, ay, off);
        az += __shfl_xor_sync(0xffffffffu, az, off);
        aw += __shfl_xor_sync(0xffffffffu, aw, off);
    }
    int c0 = 2 * lane, c1 = c0 + 1;
    float s0 = ax * __ldg(W1 + c0) + ay * __ldg(W1 + 64 + c0)
             + az * __ldg(W1 + 128 + c0) + aw * __ldg(W1 + 192 + c0) + __ldg(b1 + c0);
    float s1 = ax * __ldg(W1 + c1) + ay * __ldg(W1 + 64 + c1)
             + az * __ldg(W1 + 128 + c1) + aw * __ldg(W1 + 192 + c1) + __ldg(b1 + c1);
    g_h1h[(size_t)w * 32 + lane] = __floats2half2_rn(fmaxf(s0, 0.f), fmaxf(s1, 0.f));
}

// -------- 5: fused layer-2 agg (edge-balanced) + tiled dense + P,Q --------
__global__ void k_agg_dense2(const float* __restrict__ W2, const float* __restrict__ b2,
                             const float* __restrict__ Wm1, const float* __restrict__ bm1) {
    __shared__ float sWa[64 * PAD];
    __shared__ float sWb[64 * PAD];
    __shared__ float sIn[16 * PAD];
    __shared__ int   sRow[17];
    int tid  = threadIdx.x;
    int nb   = blockIdx.x * 16;
    int wid  = tid >> 5, lane = tid & 31;

    if (tid < 17) sRow[tid] = g_row[nb + tid];
    for (int i = tid; i < 16 * PAD; i += 512) sIn[i] = 0.f;
    __syncthreads();

    // ---- stage A: balanced edge aggregation ----
    {
        int R0 = sRow[0], R1 = sRow[16];
        int total = R1 - R0;
        int chunk = (total + 15) >> 4;
        int s = R0 + wid * chunk;
        int epos = s + chunk; if (epos > R1) epos = R1;
        if (s < epos) {
            int lo = 0, hi = 16;
            while (lo < hi) {
                int mid = (lo + hi + 1) >> 1;
                if (sRow[mid] <= s) lo = mid; else hi = mid - 1;
            }
            int cur = lo;
            int r = s;
            while (r < epos) {
                while (r >= sRow[cur + 1]) cur++;
                int seg = sRow[cur + 1]; if (seg > epos) seg = epos;
                float a0 = 0.f, a1 = 0.f;
                for (; r + 3 < seg; r += 4) {
                    int2 ev[4];
#pragma unroll
                    for (int u = 0; u < 4; u++) ev[u] = g_e[r + u];
                    __half2 hv[4];
#pragma unroll
                    for (int u = 0; u < 4; u++) hv[u] = g_h1h[(size_t)ev[u].x * 32 + lane];
#pragma unroll
                    for (int u = 0; u < 4; u++) {
                        float2 v = __half22float2(hv[u]);
                        float we = __int_as_float(ev[u].y);
                        a0 += v.x * we;
                        a1 += v.y * we;
                    }
                }
                for (; r < seg; r++) {
                    int2 ev = g_e[r];
                    float2 v = __half22float2(g_h1h[(size_t)ev.x * 32 + lane]);
                    float we = __int_as_float(ev.y);
                    a0 += v.x * we;
                    a1 += v.y * we;
                }
                atomicAdd(&sIn[cur * PAD + 2 * lane],     a0);
                atomicAdd(&sIn[cur * PAD + 2 * lane + 1], a1);
            }
        }
        int node = nb + wid;                 // self-loop term
        float dd = g_dis[node]; dd *= dd;
        float2 v = __half22float2(g_h1h[(size_t)node * 32 + lane]);
        atomicAdd(&sIn[wid * PAD + 2 * lane],     v.x * dd);
        atomicAdd(&sIn[wid * PAD + 2 * lane + 1], v.y * dd);
    }
    for (int i = tid; i < 4096; i += 512)
        sWa[(i & 63) * PAD + (i >> 6)] = W2[i];
    __syncthreads();

    // ---- stage B: h2 = relu(tmp @ W2 + b2), register-tiled ----
    int col = tid & 63, ng = tid >> 6;
    float hreg[2];
    {
        const float4* wp = reinterpret_cast<const float4*>(sWa + col * PAD);
        const float4* i0 = reinterpret_cast<const float4*>(sIn + ng * PAD);
        const float4* i1 = reinterpret_cast<const float4*>(sIn + (ng + 8) * PAD);
        float a0 = 0.f, a1 = 0.f;
#pragma unroll
        for (int k4 = 0; k4 < 16; k4++) {
            float4 w = wp[k4];
            float4 v0 = i0[k4];
            float4 v1 = i1[k4];
            a0 += v0.x * w.x + v0.y * w.y + v0.z * w.z + v0.w * w.w;
            a1 += v1.x * w.x + v1.y * w.y + v1.z * w.z + v1.w * w.w;
        }
        float bb = __ldg(b2 + col);
        hreg[0] = fmaxf(a0 + bb, 0.f);
        hreg[1] = fmaxf(a1 + bb, 0.f);
    }
    __syncthreads();

    // ---- stage C: P,Q = h2 @ Wm1 halves, register-tiled ----
    sIn[ng * PAD + col]       = hreg[0];
    sIn[(ng + 8) * PAD + col] = hreg[1];
    for (int i = tid; i < 4096; i += 512) {
        int k = i >> 6, c = i & 63;
        sWa[c * PAD + k] = Wm1[i];
        sWb[c * PAD + k] = Wm1[4096 + i];
    }
    __syncthreads();
    {
        const float4* wa = reinterpret_cast<const float4*>(sWa + col * PAD);
        const float4* wb = reinterpret_cast<const float4*>(sWb + col * PAD);
        const float4* i0 = reinterpret_cast<const float4*>(sIn + ng * PAD);
        const float4* i1 = reinterpret_cast<const float4*>(sIn + (ng + 8) * PAD);
        float p0 = 0.f, p1 = 0.f, q0 = 0.f, q1 = 0.f;
#pragma unroll
        for (int k4 = 0; k4 < 16; k4++) {
            float4 a = wa[k4];
            float4 b = wb[k4];
            float4 v0 = i0[k4];
            float4 v1 = i1[k4];
            p0 += v0.x * a.x + v0.y * a.y + v0.z * a.z + v0.w * a.w;
            q0 += v0.x * b.x + v0.y * b.y + v0.z * b.z + v0.w * b.w;
            p1 += v1.x * a.x + v1.y * a.y + v1.z * a.z + v1.w * a.w;
            q1 += v1.x * b.x + v1.y * b.y + v1.z * b.z + v1.w * b.w;
        }
        float bmv = __ldg(bm1 + col);
        size_t o0 = (size_t)(nb + ng) * 64 + col;
        size_t o1 = (size_t)(nb + ng + 8) * 64 + col;
        g_Ph[o0] = __float2half(p0 + bmv);
        g_Qh[o0] = __float2half(q0);
        g_Ph[o1] = __float2half(p1 + bmv);
        g_Qh[o1] = __float2half(q1);
    }
}

// -------- 6: edge epilogue, 8 lanes/edge, uint4 fp16 loads, fp32 math -------
__global__ void k_edge(const int* __restrict__ src, const int* __restrict__ dst,
                       const float* __restrict__ ea,
                       const float* __restrict__ Wm1,
                       const float* __restrict__ Wm2, const float* __restrict__ bm2,
                       float* __restrict__ out) {
    int l  = threadIdx.x & 7;
    int c0 = l * 8;                       // 8 columns per lane
    float w0[8], w1[8], w2[8], w3[8], wo[8];
#pragma unroll
    for (int j = 0; j < 8; j++) {
        w0[j] = __ldg(Wm1 + 128 * 64 + c0 + j);
        w1[j] = __ldg(Wm1 + 129 * 64 + c0 + j);
        w2[j] = __ldg(Wm1 + 130 * 64 + c0 + j);
        w3[j] = __ldg(Wm1 + 131 * 64 + c0 + j);
        wo[j] = __ldg(Wm2 + c0 + j);
    }
    float ob = bm2[0];

    int grp  = (blockIdx.x * blockDim.x + threadIdx.x) >> 3;
    int ngrp = (gridDim.x * blockDim.x) >> 3;
    for (int e0 = grp; e0 < NE; e0 += 4 * ngrp) {
        float part[4];
        int   ee[4];
        bool  ok[4];
#pragma unroll
        for (int u = 0; u < 4; u++) {
            int e = e0 + u * ngrp;
            ok[u] = (e < NE);
            ee[u] = ok[u] ? e : e0;
            int s = src[ee[u]], d = dst[ee[u]];
            uint4 pv = *reinterpret_cast<const uint4*>(g_Ph + (size_t)s * 64 + c0);
            uint4 qv = *reinterpret_cast<const uint4*>(g_Qh + (size_t)d * 64 + c0);
            float4 a = *reinterpret_cast<const float4*>(ea + (size_t)ee[u] * 4);
            const __half2* ph = reinterpret_cast<const __half2*>(&pv);
            const __half2* qh = reinterpret_cast<const __half2*>(&qv);
            float acc = 0.f;
#pragma unroll
            for (int j = 0; j < 4; j++) {
                float2 p = __half22float2(ph[j]);
                float2 q = __half22float2(qh[j]);
                float za = p.x + q.x + a.x * w0[2*j]   + a.y * w1[2*j]   + a.z * w2[2*j]   + a.w * w3[2*j];
                float zb = p.y + q.y + a.x * w0[2*j+1] + a.y * w1[2*j+1] + a.z * w2[2*j+1] + a.w * w3[2*j+1];
                za = fmaxf(za, 0.f);
                zb = fmaxf(zb, 0.f);
                acc += za * wo[2*j] + zb * wo[2*j+1];
            }
            part[u] = acc;
        }
#pragma unroll
        for (int off = 4; off >= 1; off >>= 1) {
#pragma unroll
            for (int u = 0; u < 4; u++)
                part[u] += __shfl_down_sync(0xffffffffu, part[u], off, 8);
        }
        if (l == 0) {
#pragma unroll
            for (int u = 0; u < 4; u++)
                if (ok[u]) out[ee[u]] = part[u] + ob;
        }
    }
}

extern "C" void kernel_launch(void* const* d_in, const int* in_sizes, int n_in,
                              void* d_out, int out_size) {
    const float* x   = (const float*)d_in[0];
    const int*   ei  = (const int*)  d_in[1];   // [2, NE] int32
    const float* ea  = (const float*)d_in[2];
    const float* W1  = (const float*)d_in[3];
    const float* b1  = (const float*)d_in[4];
    const float* W2  = (const float*)d_in[5];
    const float* b2  = (const float*)d_in[6];
    const float* Wm1 = (const float*)d_in[7];
    const float* bm1 = (const float*)d_in[8];
    const float* Wm2 = (const float*)d_in[9];
    const float* bm2 = (const float*)d_in[10];
    float* out = (float*)d_out;

    const int* src = ei;
    const int* dst = ei + NE;

    const int TB = 256;
    int ne_blk  = (NE + TB - 1) / TB;
    int agg_blk = (NN + 7) / 8;

    // no memsets: g_cnt self-cleans in k_scan; g_look is epoch-tagged.
    k_hist <<<ne_blk, TB>>>(dst);                        // op 1
    k_scan <<<NB, SCAN_B>>>();                           // op 2
    k_place<<<ne_blk, TB>>>(src, dst);                   // op 3
    k_aggx_h1<<<agg_blk, TB>>>(x, W1, b1);               // op 4
    k_agg_dense2<<<NN / 16, 512>>>(W2, b2, Wm1, bm1);    // op 5
    k_edge <<<2368, TB>>>(src, dst, ea, Wm1, Wm2, bm2, out);  // op 6 (capture slot)
}

// round 17
// speedup vs baseline: 1.1725x; 1.1689x over previous
#include <cuda_runtime.h>
#include <cuda_fp16.h>

#define NN 100000
#define NE 3200000
#define H  64
#define SCAN_B 1024
#define NB 98                      // ceil(NN / SCAN_B)
#define PAD 68                     // 64 + 4: 16B-aligned, conflict-free LDS.128

// -------- device scratch (no allocations allowed; zero-initialized at load) --------
__device__ int      g_cnt[NN];       // self-cleaning: k_scan zeroes after reading
__device__ int      g_row[NN + 1];
__device__ int      g_pos[NN];
__device__ float    g_dis[NN];
__device__ unsigned g_epoch;         // bumped once per launch by k_hist
__device__ unsigned long long g_look[NB];   // epoch<<48 | status<<46 | value
__device__ int2     g_e[NE];         // CSR slot: (src, bitcast weight)
__device__ __half2  g_h1h[NN * 32];  // h1 fp16 pairs (cols 2l, 2l+1)
__device__ __half   g_Ph[NN * H];    // fp16: h2 @ Wm1[0:64] + bm1
__device__ __half   g_Qh[NN * H];    // fp16: h2 @ Wm1[64:128]

// -------- 1: histogram of in-degrees (+ epoch bump) --------
__global__ void k_hist(const int* __restrict__ dst) {
    if (blockIdx.x == 0 && threadIdx.x == 0) g_epoch = g_epoch + 1;
    int e = blockIdx.x * blockDim.x + threadIdx.x;
    if (e < NE) atomicAdd(&g_cnt[dst[e]], 1);
}

// -------- 2: single-kernel exclusive scan (epoch-tagged decoupled lookback) --------
__global__ void k_scan() {
    __shared__ int ss[SCAN_B];
    __shared__ int s_base;
    int tid = threadIdx.x, bid = blockIdx.x;
    int i = bid * SCAN_B + tid;
    int v = 0;
    if (i < NN) {
        v = g_cnt[i];
        g_cnt[i] = 0;                 // self-clean for next graph replay
    }
    ss[tid] = v;
    __syncthreads();
#pragma unroll
    for (int off = 1; off < SCAN_B; off <<= 1) {
        int t = (tid >= off) ? ss[tid - off] : 0;
        __syncthreads();
        ss[tid] += t;
        __syncthreads();
    }
    int incl  = ss[tid];
    int total = ss[SCAN_B - 1];
    if (tid == 0) {
        unsigned long long ep = (unsigned long long)(g_epoch & 0xFFFFu) << 48;
        unsigned long long st = (bid == 0) ? (2ULL << 46) : (1ULL << 46);
        atomicExch(&g_look[bid], ep | st | (unsigned long long)(unsigned)total);
        int base = 0;
        if (bid > 0) {
            int j = bid - 1;
            while (true) {
                unsigned long long v2;
                do {
                    v2 = atomicOr(&g_look[j], 0ULL);
                } while ((v2 >> 48) != (ep >> 48) || ((v2 >> 46) & 3ULL) == 0ULL);
                base += (int)(v2 & 0xFFFFFFFFULL);
                if (((v2 >> 46) & 3ULL) == 2ULL) break;
                j--;
            }
            atomicExch(&g_look[bid],
                       ep | (2ULL << 46) | (unsigned long long)(unsigned)(base + total));
        }
        s_base = base;
    }
    __syncthreads();
    int base = s_base;
    if (i < NN) {
        int r = incl - v + base;
        g_row[i] = r;
        g_pos[i] = r;
        g_dis[i] = rsqrtf((float)(v + 1));   // +1 self-loop
    }
    if (i == 0) g_row[NN] = NE;
}

// -------- 3: CSR placement --------
__global__ void k_place(const int* __restrict__ src, const int* __restrict__ dst) {
    int e = blockIdx.x * blockDim.x + threadIdx.x;
    if (e >= NE) return;
    int s = src[e], d = dst[e];
    int idx = atomicAdd(&g_pos[d], 1);
    int2 ev; ev.x = s; ev.y = __float_as_int(g_dis[s] * g_dis[d]);
    g_e[idx] = ev;
}

// -------- 4: fused layer 1: warp per node; h1 out in fp16 pairs --------
__global__ void k_aggx_h1(const float* __restrict__ x,
                          const float* __restrict__ W1, const float* __restrict__ b1) {
    int w = (blockIdx.x * blockDim.x + threadIdx.x) >> 5;
    if (w >= NN) return;
    int lane = threadIdx.x & 31;
    int r0 = g_row[w], r1 = g_row[w + 1];
    float ax = 0.f, ay = 0.f, az = 0.f, aw = 0.f;
#pragma unroll 4
    for (int r = r0 + lane; r < r1; r += 32) {
        int2 ev = g_e[r];
        float ww = __int_as_float(ev.y);
        float4 xv = *reinterpret_cast<const float4*>(x + (size_t)ev.x * 4);
        ax += xv.x * ww; ay += xv.y * ww; az += xv.z * ww; aw += xv.w * ww;
    }
    if (lane == 0) {                     // self-loop
        float dd = g_dis[w]; dd *= dd;
        float4 xv = *reinterpret_cast<const float4*>(x + (size_t)w * 4);
        ax += dd * xv.x; ay += dd * xv.y; az += dd * xv.z; aw += dd * xv.w;
    }
#pragma unroll
    for (int off = 16; off >= 1; off >>= 1) {
        ax += __shfl_xor_sync(0xffffffffu, ax, off);
        ay += __shfl_xor_sync(0xffffffffu, ay, off);
        az += __shfl_xor_sync(0xffffffffu, az, off);
        aw += __shfl_xor_sync(0xffffffffu, aw, off);
    }
    int c0 = 2 * lane, c1 = c0 + 1;
    float s0 = ax * __ldg(W1 + c0) + ay * __ldg(W1 + 64 + c0)
             + az * __ldg(W1 + 128 + c0) + aw * __ldg(W1 + 192 + c0) + __ldg(b1 + c0);
    float s1 = ax * __ldg(W1 + c1) + ay * __ldg(W1 + 64 + c1)
             + az * __ldg(W1 + 128 + c1) + aw * __ldg(W1 + 192 + c1) + __ldg(b1 + c1);
    g_h1h[(size_t)w * 32 + lane] = __floats2half2_rn(fmaxf(s0, 0.f), fmaxf(s1, 0.f));
}

// -------- 5: fused layer-2 agg (edge-balanced) + tiled dense + P,Q --------
__global__ void k_agg_dense2(const float* __restrict__ W2, const float* __restrict__ b2,
                             const float* __restrict__ Wm1, const float* __restrict__ bm1) {
    __shared__ float sWa[64 * PAD];
    __shared__ float sWb[64 * PAD];
    __shared__ float sIn[16 * PAD];
    __shared__ int   sRow[17];
    int tid  = threadIdx.x;
    int nb   = blockIdx.x * 16;
    int wid  = tid >> 5, lane = tid & 31;

    if (tid < 17) sRow[tid] = g_row[nb + tid];
    for (int i = tid; i < 16 * PAD; i += 512) sIn[i] = 0.f;
    __syncthreads();

    // ---- stage A: balanced edge aggregation ----
    {
        int R0 = sRow[0], R1 = sRow[16];
        int total = R1 - R0;
        int chunk = (total + 15) >> 4;
        int s = R0 + wid * chunk;
        int epos = s + chunk; if (epos > R1) epos = R1;
        if (s < epos) {
            int lo = 0, hi = 16;
            while (lo < hi) {
                int mid = (lo + hi + 1) >> 1;
                if (sRow[mid] <= s) lo = mid; else hi = mid - 1;
            }
            int cur = lo;
            int r = s;
            while (r < epos) {
                while (r >= sRow[cur + 1]) cur++;
                int seg = sRow[cur + 1]; if (seg > epos) seg = epos;
                float a0 = 0.f, a1 = 0.f;
                for (; r + 3 < seg; r += 4) {
                    int2 ev[4];
#pragma unroll
                    for (int u = 0; u < 4; u++) ev[u] = g_e[r + u];
                    __half2 hv[4];
#pragma unroll
                    for (int u = 0; u < 4; u++) hv[u] = g_h1h[(size_t)ev[u].x * 32 + lane];
#pragma unroll
                    for (int u = 0; u < 4; u++) {
                        float2 v = __half22float2(hv[u]);
                        float we = __int_as_float(ev[u].y);
                        a0 += v.x * we;
                        a1 += v.y * we;
                    }
                }
                for (; r < seg; r++) {
                    int2 ev = g_e[r];
                    float2 v = __half22float2(g_h1h[(size_t)ev.x * 32 + lane]);
                    float we = __int_as_float(ev.y);
                    a0 += v.x * we;
                    a1 += v.y * we;
                }
                atomicAdd(&sIn[cur * PAD + 2 * lane],     a0);
                atomicAdd(&sIn[cur * PAD + 2 * lane + 1], a1);
            }
        }
        int node = nb + wid;                 // self-loop term
        float dd = g_dis[node]; dd *= dd;
        float2 v = __half22float2(g_h1h[(size_t)node * 32 + lane]);
        atomicAdd(&sIn[wid * PAD + 2 * lane],     v.x * dd);
        atomicAdd(&sIn[wid * PAD + 2 * lane + 1], v.y * dd);
    }
    for (int i = tid; i < 4096; i += 512)
        sWa[(i & 63) * PAD + (i >> 6)] = W2[i];
    __syncthreads();

    // ---- stage B: h2 = relu(tmp @ W2 + b2), register-tiled ----
    int col = tid & 63, ng = tid >> 6;
    float hreg[2];
    {
        const float4* wp = reinterpret_cast<const float4*>(sWa + col * PAD);
        const float4* i0 = reinterpret_cast<const float4*>(sIn + ng * PAD);
        const float4* i1 = reinterpret_cast<const float4*>(sIn + (ng + 8) * PAD);
        float a0 = 0.f, a1 = 0.f;
#pragma unroll
        for (int k4 = 0; k4 < 16; k4++) {
            float4 w = wp[k4];
            float4 v0 = i0[k4];
            float4 v1 = i1[k4];
            a0 += v0.x * w.x + v0.y * w.y + v0.z * w.z + v0.w * w.w;
            a1 += v1.x * w.x + v1.y * w.y + v1.z * w.z + v1.w * w.w;
        }
        float bb = __ldg(b2 + col);
        hreg[0] = fmaxf(a0 + bb, 0.f);
        hreg[1] = fmaxf(a1 + bb, 0.f);
    }
    __syncthreads();

    // ---- stage C: P,Q = h2 @ Wm1 halves, register-tiled ----
    sIn[ng * PAD + col]       = hreg[0];
    sIn[(ng + 8) * PAD + col] = hreg[1];
    for (int i = tid; i < 4096; i += 512) {
        int k = i >> 6, c = i & 63;
        sWa[c * PAD + k] = Wm1[i];
        sWb[c * PAD + k] = Wm1[4096 + i];
    }
    __syncthreads();
    {
        const float4* wa = reinterpret_cast<const float4*>(sWa + col * PAD);
        const float4* wb = reinterpret_cast<const float4*>(sWb + col * PAD);
        const float4* i0 = reinterpret_cast<const float4*>(sIn + ng * PAD);
        const float4* i1 = reinterpret_cast<const float4*>(sIn + (ng + 8) * PAD);
        float p0 = 0.f, p1 = 0.f, q0 = 0.f, q1 = 0.f;
#pragma unroll
        for (int k4 = 0; k4 < 16; k4++) {
            float4 a = wa[k4];
            float4 b = wb[k4];
            float4 v0 = i0[k4];
            float4 v1 = i1[k4];
            p0 += v0.x * a.x + v0.y * a.y + v0.z * a.z + v0.w * a.w;
            q0 += v0.x * b.x + v0.y * b.y + v0.z * b.z + v0.w * b.w;
            p1 += v1.x * a.x + v1.y * a.y + v1.z * a.z + v1.w * a.w;
            q1 += v1.x * b.x + v1.y * b.y + v1.z * b.z + v1.w * b.w;
        }
        float bmv = __ldg(bm1 + col);
        size_t o0 = (size_t)(nb + ng) * 64 + col;
        size_t o1 = (size_t)(nb + ng + 8) * 64 + col;
        g_Ph[o0] = __float2half(p0 + bmv);
        g_Qh[o0] = __float2half(q0);
        g_Ph[o1] = __float2half(p1 + bmv);
        g_Qh[o1] = __float2half(q1);
    }
}

// -------- 6: edge epilogue: half2 z-compute, fp32 final dot --------
// out[e] = relu(P[s]+Q[d]+ea@Wea) @ Wm2 + bm2
__global__ void k_edge(const int* __restrict__ src, const int* __restrict__ dst,
                       const float* __restrict__ ea,
                       const float* __restrict__ Wm1,
                       const float* __restrict__ Wm2, const float* __restrict__ bm2,
                       float* __restrict__ out) {
    int l  = threadIdx.x & 7;
    int c0 = l * 8;                       // 8 columns per lane
    __half2 wh[4][4];                     // Wea rows k=0..3 at my 8 cols
#pragma unroll
    for (int k = 0; k < 4; k++)
#pragma unroll
        for (int j = 0; j < 4; j++)
            wh[k][j] = __floats2half2_rn(__ldg(Wm1 + (128 + k) * 64 + c0 + 2 * j),
                                         __ldg(Wm1 + (128 + k) * 64 + c0 + 2 * j + 1));
    float wo[8];
#pragma unroll
    for (int j = 0; j < 8; j++) wo[j] = __ldg(Wm2 + c0 + j);
    const __half2 zero2 = __float2half2_rn(0.f);
    float ob = bm2[0];

    int grp  = (blockIdx.x * blockDim.x + threadIdx.x) >> 3;
    int ngrp = (gridDim.x * blockDim.x) >> 3;
    for (int e0 = grp; e0 < NE; e0 += 4 * ngrp) {
        float part[4];
        int   ee[4];
        bool  ok[4];
#pragma unroll
        for (int u = 0; u < 4; u++) {
            int e = e0 + u * ngrp;
            ok[u] = (e < NE);
            ee[u] = ok[u] ? e : e0;
            int s = src[ee[u]], d = dst[ee[u]];
            uint4 pv = *reinterpret_cast<const uint4*>(g_Ph + (size_t)s * 64 + c0);
            uint4 qv = *reinterpret_cast<const uint4*>(g_Qh + (size_t)d * 64 + c0);
            float4 a = *reinterpret_cast<const float4*>(ea + (size_t)ee[u] * 4);
            const __half2* ph = reinterpret_cast<const __half2*>(&pv);
            const __half2* qh = reinterpret_cast<const __half2*>(&qv);
            __half2 eh0 = __float2half2_rn(a.x);
            __half2 eh1 = __float2half2_rn(a.y);
            __half2 eh2 = __float2half2_rn(a.z);
            __half2 eh3 = __float2half2_rn(a.w);
            float acc = 0.f;
#pragma unroll
            for (int j = 0; j < 4; j++) {
                __half2 z = __hadd2(ph[j], qh[j]);
                z = __hfma2(eh0, wh[0][j], z);
                z = __hfma2(eh1, wh[1][j], z);
                z = __hfma2(eh2, wh[2][j], z);
                z = __hfma2(eh3, wh[3][j], z);
                z = __hmax2(z, zero2);
                float2 zf = __half22float2(z);       // fp32 final dot
                acc += zf.x * wo[2 * j] + zf.y * wo[2 * j + 1];
            }
            part[u] = acc;
        }
#pragma unroll
        for (int off = 4; off >= 1; off >>= 1) {
#pragma unroll
            for (int u = 0; u < 4; u++)
                part[u] += __shfl_down_sync(0xffffffffu, part[u], off, 8);
        }
        if (l == 0) {
#pragma unroll
            for (int u = 0; u < 4; u++)
                if (ok[u]) out[ee[u]] = part[u] + ob;
        }
    }
}

extern "C" void kernel_launch(void* const* d_in, const int* in_sizes, int n_in,
                              void* d_out, int out_size) {
    const float* x   = (const float*)d_in[0];
    const int*   ei  = (const int*)  d_in[1];   // [2, NE] int32
    const float* ea  = (const float*)d_in[2];
    const float* W1  = (const float*)d_in[3];
    const float* b1  = (const float*)d_in[4];
    const float* W2  = (const float*)d_in[5];
    const float* b2  = (const float*)d_in[6];
    const float* Wm1 = (const float*)d_in[7];
    const float* bm1 = (const float*)d_in[8];
    const float* Wm2 = (const float*)d_in[9];
    const float* bm2 = (const float*)d_in[10];
    float* out = (float*)d_out;

    const int* src = ei;
    const int* dst = ei + NE;

    const int TB = 256;
    int ne_blk  = (NE + TB - 1) / TB;
    int agg_blk = (NN + 7) / 8;

    // no memsets: g_cnt self-cleans in k_scan; g_look is epoch-tagged.
    k_hist <<<ne_blk, TB>>>(dst);                        // op 1
    k_scan <<<NB, SCAN_B>>>();                           // op 2
    k_place<<<ne_blk, TB>>>(src, dst);                   // op 3
    k_aggx_h1<<<agg_blk, TB>>>(x, W1, b1);               // op 4 (capture slot)
    k_agg_dense2<<<NN / 16, 512>>>(W2, b2, Wm1, bm1);    // op 5
    k_edge <<<2368, TB>>>(src, dst, ea, Wm1, Wm2, bm2, out);  // op 6
}